// round 1
// baseline (speedup 1.0000x reference)
#include <cuda_runtime.h>
#include <cuda_bf16.h>
#include <math.h>

// Problem constants (fixed by the reference setup)
constexpr int B    = 32;
constexpr int H    = 32;
constexpr int HKV  = 8;
constexpr int GRP  = H / HKV;     // 4
constexpr int D    = 128;
constexpr int BS   = 16;          // tokens per page
constexpr int BPS  = 128;         // blocks per sequence
constexpr int NSPLIT = 8;
constexpr int SPLIT  = 256;       // tokens per split (8*256 = 2048 max ctx)
constexpr float SCALE = 0.08838834764831845f; // 128^-0.5

// Partial results (unnormalized): [B, HKV, NSPLIT, GRP, D] and stats [B,HKV,NSPLIT,GRP]
__device__ float g_pout[B * HKV * NSPLIT * GRP * D];
__device__ float g_pm[B * HKV * NSPLIT * GRP];
__device__ float g_pl[B * HKV * NSPLIT * GRP];

// ---------------------------------------------------------------------------
// Kernel 1: split-KV attention partials. One CTA = (b, kvh, split).
// 256 threads = 8 warps; warp w handles tokens t0+w, t0+w+8, ...
// Lane j holds D elements [4j, 4j+4).
// ---------------------------------------------------------------------------
__global__ __launch_bounds__(256, 4)
void attn_split_kernel(const float* __restrict__ q,
                       const float* __restrict__ knew,
                       const float* __restrict__ vnew,
                       const float* __restrict__ kc,
                       const float* __restrict__ vc,
                       const int*   __restrict__ btab,
                       const int*   __restrict__ clen)
{
    const int cta   = blockIdx.x;
    const int split = cta % NSPLIT;
    const int kvh   = (cta / NSPLIT) % HKV;
    const int b     = cta / (NSPLIT * HKV);
    const int tid   = threadIdx.x;
    const int wid   = tid >> 5;
    const int lane  = tid & 31;

    const int ctx  = clen[b];
    const int t0   = split * SPLIT;
    const int pbase = ((b * HKV + kvh) * NSPLIT + split) * GRP;

    if (t0 >= ctx) {
        // empty split: mark invalid
        if (tid < GRP) { g_pm[pbase + tid] = -INFINITY; g_pl[pbase + tid] = 0.0f; }
        return;
    }
    const int t1   = min(t0 + SPLIT, ctx);
    const int last = ctx - 1;                 // new-token index
    const int tcut = min(t1, last);           // cached-token upper bound

    __shared__ float qs[GRP][D];
    __shared__ float cs[D], sn[D];

    // RoPE tables at position p = ctx, bf16-faithful (inv_freq, t, freq, cos, sin all bf16-rounded)
    if (tid < 64) {
        int i = tid;
        float invf = __bfloat162float(__float2bfloat16(1.0f / powf(10000.0f, (float)i * (1.0f / 64.0f))));
        float tb   = __bfloat162float(__float2bfloat16((float)ctx));
        float fr   = __bfloat162float(__float2bfloat16(tb * invf));
        float c = __bfloat162float(__float2bfloat16((float)cos((double)fr)));
        float s = __bfloat162float(__float2bfloat16((float)sin((double)fr)));
        cs[i] = c; cs[i + 64] = c;
        sn[i] = s; sn[i + 64] = s;
    }
    __syncthreads();

    // RoPE the 4 query heads of this kv group into smem
    for (int idx = tid; idx < GRP * D; idx += 256) {
        int g = idx >> 7, d = idx & 127;
        const float* qp = q + ((size_t)(b * H + kvh * GRP + g)) * D;
        float x   = qp[d];
        float rot = (d < 64) ? -qp[d + 64] : qp[d - 64];
        qs[g][d] = x * cs[d] + rot * sn[d];
    }
    __syncthreads();

    // per-warp online softmax state
    float  m[GRP], l[GRP];
    float4 acc[GRP];
#pragma unroll
    for (int g = 0; g < GRP; g++) {
        m[g] = -INFINITY; l[g] = 0.0f;
        acc[g] = make_float4(0.f, 0.f, 0.f, 0.f);
    }

    const float4 qv0 = *reinterpret_cast<const float4*>(&qs[0][lane * 4]);
    const float4 qv1 = *reinterpret_cast<const float4*>(&qs[1][lane * 4]);
    const float4 qv2 = *reinterpret_cast<const float4*>(&qs[2][lane * 4]);
    const float4 qv3 = *reinterpret_cast<const float4*>(&qs[3][lane * 4]);

    auto process = [&](float4 k4, float4 v4) {
        float p0 = k4.x * qv0.x + k4.y * qv0.y + k4.z * qv0.z + k4.w * qv0.w;
        float p1 = k4.x * qv1.x + k4.y * qv1.y + k4.z * qv1.z + k4.w * qv1.w;
        float p2 = k4.x * qv2.x + k4.y * qv2.y + k4.z * qv2.z + k4.w * qv2.w;
        float p3 = k4.x * qv3.x + k4.y * qv3.y + k4.z * qv3.z + k4.w * qv3.w;
#pragma unroll
        for (int o = 16; o; o >>= 1) {
            p0 += __shfl_xor_sync(0xffffffffu, p0, o);
            p1 += __shfl_xor_sync(0xffffffffu, p1, o);
            p2 += __shfl_xor_sync(0xffffffffu, p2, o);
            p3 += __shfl_xor_sync(0xffffffffu, p3, o);
        }
        float sc[GRP] = { p0 * SCALE, p1 * SCALE, p2 * SCALE, p3 * SCALE };
#pragma unroll
        for (int g = 0; g < GRP; g++) {
            float mn   = fmaxf(m[g], sc[g]);
            float corr = __expf(m[g] - mn);
            float p    = __expf(sc[g] - mn);
            l[g] = l[g] * corr + p;
            acc[g].x = acc[g].x * corr + p * v4.x;
            acc[g].y = acc[g].y * corr + p * v4.y;
            acc[g].z = acc[g].z * corr + p * v4.z;
            acc[g].w = acc[g].w * corr + p * v4.w;
            m[g] = mn;
        }
    };

    // ---- main loop over cached tokens with software prefetch (MLP>=2) ----
    {
        int t = t0 + wid;
        float4 kcur = make_float4(0.f,0.f,0.f,0.f), vcur = kcur;
        if (t < tcut) {
            int blk = btab[b * BPS + (t >> 4)];
            size_t base = ((size_t)(blk * BS + (t & 15)) * HKV + kvh) * D;
            kcur = reinterpret_cast<const float4*>(kc + base)[lane];
            vcur = reinterpret_cast<const float4*>(vc + base)[lane];
        }
        while (t < tcut) {
            int tn = t + 8;
            float4 knx = make_float4(0.f,0.f,0.f,0.f), vnx = knx;
            if (tn < tcut) {
                int blk = btab[b * BPS + (tn >> 4)];
                size_t base = ((size_t)(blk * BS + (tn & 15)) * HKV + kvh) * D;
                knx = reinterpret_cast<const float4*>(kc + base)[lane];
                vnx = reinterpret_cast<const float4*>(vc + base)[lane];
            }
            process(kcur, vcur);
            kcur = knx; vcur = vnx; t = tn;
        }
    }

    // ---- the new token (index last): rope(k_new), v_new; handled by one warp ----
    if (last >= t0 && last < t1 && wid == ((last - t0) & 7)) {
        const float* kp = knew + ((size_t)(b * HKV + kvh)) * D;
        const float* vp = vnew + ((size_t)(b * HKV + kvh)) * D;
        int d0 = lane * 4;
        float kr[4], vr[4];
#pragma unroll
        for (int j = 0; j < 4; j++) {
            int d = d0 + j;
            float x   = kp[d];
            float rot = (d < 64) ? -kp[d + 64] : kp[d - 64];
            kr[j] = x * cs[d] + rot * sn[d];
            vr[j] = vp[d];
        }
        process(make_float4(kr[0], kr[1], kr[2], kr[3]),
                make_float4(vr[0], vr[1], vr[2], vr[3]));
    }

    // ---- cross-warp combine in smem ----
    __shared__ float rm[8][GRP], rl[8][GRP];
    __shared__ float racc[8][GRP][D];
#pragma unroll
    for (int g = 0; g < GRP; g++) {
        *reinterpret_cast<float4*>(&racc[wid][g][lane * 4]) = acc[g];
    }
    if (lane == 0) {
#pragma unroll
        for (int g = 0; g < GRP; g++) { rm[wid][g] = m[g]; rl[wid][g] = l[g]; }
    }
    __syncthreads();

    for (int idx = tid; idx < GRP * D; idx += 256) {
        int g = idx >> 7, d = idx & 127;
        float M = -INFINITY;
#pragma unroll
        for (int w = 0; w < 8; w++) M = fmaxf(M, rm[w][g]);
        float L = 0.f, A = 0.f;
#pragma unroll
        for (int w = 0; w < 8; w++) {
            float wgt = __expf(rm[w][g] - M);  // exp(-inf - finite) = 0 for empty warps
            L += rl[w][g] * wgt;
            A += racc[w][g][d] * wgt;
        }
        g_pout[(size_t)(pbase + g) * D + d] = A;
        if (d == 0) { g_pm[pbase + g] = M; g_pl[pbase + g] = L; }
    }
}

// ---------------------------------------------------------------------------
// Kernel 2: combine NSPLIT partials per (b, h). grid = B*H, 128 threads (one per d)
// ---------------------------------------------------------------------------
__global__ __launch_bounds__(128)
void attn_combine_kernel(float* __restrict__ out)
{
    const int bh  = blockIdx.x;
    const int b   = bh / H;
    const int h   = bh % H;
    const int kvh = h / GRP;
    const int g   = h % GRP;
    const int d   = threadIdx.x;

    float ms[NSPLIT];
    float M = -INFINITY;
#pragma unroll
    for (int s = 0; s < NSPLIT; s++) {
        ms[s] = g_pm[((b * HKV + kvh) * NSPLIT + s) * GRP + g];
        M = fmaxf(M, ms[s]);
    }
    float L = 0.f, A = 0.f;
#pragma unroll
    for (int s = 0; s < NSPLIT; s++) {
        float w = __expf(ms[s] - M);
        int pg = ((b * HKV + kvh) * NSPLIT + s) * GRP + g;
        L += g_pl[pg] * w;
        A += g_pout[(size_t)pg * D + d] * w;
    }
    out[(size_t)bh * D + d] = A / L;
}

// ---------------------------------------------------------------------------
extern "C" void kernel_launch(void* const* d_in, const int* in_sizes, int n_in,
                              void* d_out, int out_size)
{
    const float* q    = (const float*)d_in[0];   // [32,32,128]
    const float* knew = (const float*)d_in[1];   // [32,8,128]
    const float* vnew = (const float*)d_in[2];   // [32,8,128]
    const float* kc   = (const float*)d_in[3];   // [4096,16,8,128]
    const float* vc   = (const float*)d_in[4];   // [4096,16,8,128]
    const int*   btab = (const int*)d_in[5];     // [32,128]
    const int*   clen = (const int*)d_in[6];     // [32]
    float* out = (float*)d_out;                  // [32,32,128] fp32

    attn_split_kernel<<<B * HKV * NSPLIT, 256>>>(q, knew, vnew, kc, vc, btab, clen);
    attn_combine_kernel<<<B * H, 128>>>(out);
}

// round 2
// speedup vs baseline: 1.1054x; 1.1054x over previous
#include <cuda_runtime.h>
#include <cuda_bf16.h>
#include <math.h>

constexpr int B    = 32;
constexpr int H    = 32;
constexpr int HKV  = 8;
constexpr int GRP  = H / HKV;     // 4
constexpr int D    = 128;
constexpr int BPS  = 128;         // blocks per sequence
constexpr int NSPLIT = 8;
constexpr int SPLIT  = 256;       // tokens per split
constexpr float SCALE = 0.08838834764831845f;     // 128^-0.5
constexpr float LOG2E = 1.4426950408889634f;
constexpr float QF    = SCALE * LOG2E;            // folded into q
constexpr float M0C   = -16.0f * LOG2E;           // fixed softmax shift (log2 units)

// Partials: [B, HKV, NSPLIT, GRP, D] accum and [B,HKV,NSPLIT,GRP] denom (shared fixed shift M0)
__device__ float g_pout[B * HKV * NSPLIT * GRP * D];
__device__ float g_pl[B * HKV * NSPLIT * GRP];

__device__ __forceinline__ float ex2(float x) {
    float r;
    asm("ex2.approx.f32 %0, %1;" : "=f"(r) : "f"(x));
    return r;
}

// ---------------------------------------------------------------------------
// Kernel 1: split-KV partials. CTA = (b, kvh, split). 8 warps, warp w owns
// tokens t0+w, t0+w+8, ... Lane j holds d-slice [4j, 4j+4).
// ---------------------------------------------------------------------------
__global__ __launch_bounds__(256, 3)
void attn_split_kernel(const float* __restrict__ q,
                       const float* __restrict__ knew,
                       const float* __restrict__ vnew,
                       const float* __restrict__ kc,
                       const float* __restrict__ vc,
                       const int*   __restrict__ btab,
                       const int*   __restrict__ clen)
{
    const int cta   = blockIdx.x;
    const int split = cta % NSPLIT;
    const int kvh   = (cta / NSPLIT) % HKV;
    const int b     = cta / (NSPLIT * HKV);
    const int tid   = threadIdx.x;
    const int wid   = tid >> 5;
    const int lane  = tid & 31;

    const int ctx = clen[b];
    const int t0  = split * SPLIT;
    if (t0 >= ctx) return;                      // combine never reads inactive splits

    const int t1   = min(t0 + SPLIT, ctx);
    const int last = ctx - 1;                   // new-token index
    const int tcut = min(t1, last);             // cached tokens upper bound
    const int pbase = ((b * HKV + kvh) * NSPLIT + split) * GRP;

    __shared__ float qs[GRP][D];
    __shared__ float cs[D], sn[D];
    __shared__ int   bt[BPS];
    __shared__ float rl[8][GRP];
    __shared__ float racc[8][GRP][D];

    if (tid < BPS) bt[tid] = btab[b * BPS + tid];

    // bf16-faithful RoPE tables at position p = ctx
    if (tid < 64) {
        int i = tid;
        float invf = __bfloat162float(__float2bfloat16(1.0f / powf(10000.0f, (float)i * (1.0f / 64.0f))));
        float tb   = __bfloat162float(__float2bfloat16((float)ctx));
        float fr   = __bfloat162float(__float2bfloat16(tb * invf));
        float c = __bfloat162float(__float2bfloat16((float)cos((double)fr)));
        float s = __bfloat162float(__float2bfloat16((float)sin((double)fr)));
        cs[i] = c; cs[i + 64] = c;
        sn[i] = s; sn[i + 64] = s;
    }
    __syncthreads();

    // RoPE q, pre-scaled by SCALE*log2(e)
    for (int idx = tid; idx < GRP * D; idx += 256) {
        int g = idx >> 7, d = idx & 127;
        const float* qp = q + ((size_t)(b * H + kvh * GRP + g)) * D;
        float x   = qp[d];
        float rot = (d < 64) ? -qp[d + 64] : qp[d - 64];
        qs[g][d] = (x * cs[d] + rot * sn[d]) * QF;
    }
    __syncthreads();

    const float4 qv0 = *reinterpret_cast<const float4*>(&qs[0][lane * 4]);
    const float4 qv1 = *reinterpret_cast<const float4*>(&qs[1][lane * 4]);
    const float4 qv2 = *reinterpret_cast<const float4*>(&qs[2][lane * 4]);
    const float4 qv3 = *reinterpret_cast<const float4*>(&qs[3][lane * 4]);

    // permuted accumulators: slot j on this lane = head (j ^ (lane>>3))
    float  l0 = 0.f, l1 = 0.f, l2 = 0.f, l3 = 0.f;
    float4 a0 = make_float4(0,0,0,0), a1 = a0, a2 = a0, a3 = a0;

    const bool hi16 = (lane & 16) != 0;
    const bool hi8  = (lane & 8)  != 0;

    auto process = [&](float4 k4, float4 v4) {
        float p0 = k4.x*qv0.x + k4.y*qv0.y + k4.z*qv0.z + k4.w*qv0.w;
        float p1 = k4.x*qv1.x + k4.y*qv1.y + k4.z*qv1.z + k4.w*qv1.w;
        float p2 = k4.x*qv2.x + k4.y*qv2.y + k4.z*qv2.z + k4.w*qv2.w;
        float p3 = k4.x*qv3.x + k4.y*qv3.y + k4.z*qv3.z + k4.w*qv3.w;
        // multi-value allreduce: 9 shuffles, heads end permuted by lane group
        float gA0 = hi16 ? p0 : p2;
        float gA1 = hi16 ? p1 : p3;
        float r0  = hi16 ? p2 : p0;
        float r1  = hi16 ? p3 : p1;
        r0 += __shfl_xor_sync(0xffffffffu, gA0, 16);
        r1 += __shfl_xor_sync(0xffffffffu, gA1, 16);
        float gB = hi8 ? r0 : r1;
        float r  = hi8 ? r1 : r0;
        r += __shfl_xor_sync(0xffffffffu, gB, 8);
        r += __shfl_xor_sync(0xffffffffu, r, 4);
        r += __shfl_xor_sync(0xffffffffu, r, 2);
        r += __shfl_xor_sync(0xffffffffu, r, 1);
        float s1 = __shfl_xor_sync(0xffffffffu, r, 8);
        float s2 = __shfl_xor_sync(0xffffffffu, r, 16);
        float s3 = __shfl_xor_sync(0xffffffffu, r, 24);
        float p;
        p = ex2(r  + M0C); l0 += p;
        a0.x += p*v4.x; a0.y += p*v4.y; a0.z += p*v4.z; a0.w += p*v4.w;
        p = ex2(s1 + M0C); l1 += p;
        a1.x += p*v4.x; a1.y += p*v4.y; a1.z += p*v4.z; a1.w += p*v4.w;
        p = ex2(s2 + M0C); l2 += p;
        a2.x += p*v4.x; a2.y += p*v4.y; a2.z += p*v4.z; a2.w += p*v4.w;
        p = ex2(s3 + M0C); l3 += p;
        a3.x += p*v4.x; a3.y += p*v4.y; a3.z += p*v4.z; a3.w += p*v4.w;
    };

    const float4* kc4 = reinterpret_cast<const float4*>(kc);
    const float4* vc4 = reinterpret_cast<const float4*>(vc);
    const int hk = kvh * 32 + lane;

    // main loop, software prefetch depth 1
    {
        int t = t0 + wid;
        float4 kcur, vcur;
        if (t < tcut) {
            int idx = bt[t >> 4] * 4096 + (t & 15) * 256 + hk;
            kcur = kc4[idx];
            vcur = vc4[idx];
        }
        while (t < tcut) {
            int tn = t + 8;
            float4 knx, vnx;
            if (tn < tcut) {
                int idx = bt[tn >> 4] * 4096 + (tn & 15) * 256 + hk;
                knx = vc4 == nullptr ? kcur : kc4[idx];
                vnx = vc4[idx];
            }
            process(kcur, vcur);
            kcur = knx; vcur = vnx; t = tn;
        }
    }

    // new token: rope(k_new), v_new
    if (last >= t0 && last < t1 && wid == ((last - t0) & 7)) {
        const float* kp = knew + ((size_t)(b * HKV + kvh)) * D;
        const float* vp = vnew + ((size_t)(b * HKV + kvh)) * D;
        int d0 = lane * 4;
        float kr[4], vr[4];
#pragma unroll
        for (int j = 0; j < 4; j++) {
            int d = d0 + j;
            float x   = kp[d];
            float rot = (d < 64) ? -kp[d + 64] : kp[d - 64];
            kr[j] = x * cs[d] + rot * sn[d];
            vr[j] = vp[d];
        }
        process(make_float4(kr[0], kr[1], kr[2], kr[3]),
                make_float4(vr[0], vr[1], vr[2], vr[3]));
    }

    // cross-warp combine: plain sums (shared fixed shift M0)
    const int grp = lane >> 3;
    *reinterpret_cast<float4*>(&racc[wid][0 ^ grp][lane * 4]) = a0;
    *reinterpret_cast<float4*>(&racc[wid][1 ^ grp][lane * 4]) = a1;
    *reinterpret_cast<float4*>(&racc[wid][2 ^ grp][lane * 4]) = a2;
    *reinterpret_cast<float4*>(&racc[wid][3 ^ grp][lane * 4]) = a3;
    if (lane == 0) {  // lane 0 has grp 0: slot j == head j
        rl[wid][0] = l0; rl[wid][1] = l1; rl[wid][2] = l2; rl[wid][3] = l3;
    }
    __syncthreads();

    for (int idx = tid; idx < GRP * D; idx += 256) {
        int g = idx >> 7, d = idx & 127;
        float A = 0.f;
#pragma unroll
        for (int w = 0; w < 8; w++) A += racc[w][g][d];
        g_pout[(size_t)(pbase + g) * D + d] = A;
        if (d == 0) {
            float L = 0.f;
#pragma unroll
            for (int w = 0; w < 8; w++) L += rl[w][g];
            g_pl[pbase + g] = L;
        }
    }
}

// ---------------------------------------------------------------------------
// Kernel 2: sum active splits per (b,h), normalize. grid=B*H, 128 threads.
// ---------------------------------------------------------------------------
__global__ __launch_bounds__(128)
void attn_combine_kernel(float* __restrict__ out, const int* __restrict__ clen)
{
    const int bh  = blockIdx.x;
    const int b   = bh / H;
    const int h   = bh % H;
    const int kvh = h / GRP;
    const int g   = h % GRP;
    const int d   = threadIdx.x;

    const int ns = (clen[b] + SPLIT - 1) / SPLIT;
    float A = 0.f, L = 0.f;
#pragma unroll
    for (int s = 0; s < NSPLIT; s++) {
        if (s < ns) {
            int pg = ((b * HKV + kvh) * NSPLIT + s) * GRP + g;
            A += g_pout[(size_t)pg * D + d];
            L += g_pl[pg];
        }
    }
    out[(size_t)bh * D + d] = A / L;
}

// ---------------------------------------------------------------------------
extern "C" void kernel_launch(void* const* d_in, const int* in_sizes, int n_in,
                              void* d_out, int out_size)
{
    const float* q    = (const float*)d_in[0];
    const float* knew = (const float*)d_in[1];
    const float* vnew = (const float*)d_in[2];
    const float* kc   = (const float*)d_in[3];
    const float* vc   = (const float*)d_in[4];
    const int*   btab = (const int*)d_in[5];
    const int*   clen = (const int*)d_in[6];
    float* out = (float*)d_out;

    attn_split_kernel<<<B * HKV * NSPLIT, 256>>>(q, knew, vnew, kc, vc, btab, clen);
    attn_combine_kernel<<<B * H, 128>>>(out, clen);
}

// round 7
// speedup vs baseline: 1.1327x; 1.0247x over previous
#include <cuda_runtime.h>
#include <cuda_bf16.h>
#include <math.h>

constexpr int B    = 32;
constexpr int H    = 32;
constexpr int HKV  = 8;
constexpr int GRP  = H / HKV;     // 4
constexpr int D    = 128;
constexpr int BPS  = 128;
constexpr int NSPLIT = 8;
constexpr int SPLIT  = 256;
constexpr int NITEMS = B * HKV * NSPLIT;   // 2048
constexpr float SCALE = 0.08838834764831845f;
constexpr float LOG2E = 1.4426950408889634f;
constexpr float QF    = SCALE * LOG2E;
constexpr float M0C   = -16.0f * LOG2E;    // fixed softmax shift (log2 units)

// 16B alignment required: accessed through float4.
__device__ __align__(16) float g_pout[B * HKV * NSPLIT * GRP * D];
__device__ float g_pl[B * HKV * NSPLIT * GRP];
__device__ __align__(16) float g_qr[B][H][D];     // roped, pre-scaled q
__device__ __align__(16) float g_kn[B][HKV][D];   // roped k_new
__device__ int   g_ctr;

__device__ __forceinline__ float ex2(float x) {
    float r;
    asm("ex2.approx.f32 %0, %1;" : "=f"(r) : "f"(x));
    return r;
}

// ---------------------------------------------------------------------------
// Kernel 0: per-b prep — RoPE tables (bf16-faithful), roped q / k_new, counter reset
// ---------------------------------------------------------------------------
__global__ __launch_bounds__(256)
void prep_kernel(const float* __restrict__ q,
                 const float* __restrict__ knew,
                 const int*   __restrict__ clen)
{
    const int b   = blockIdx.x;
    const int tid = threadIdx.x;
    if (b == 0 && tid == 0) g_ctr = 0;

    __shared__ float cs[D], sn[D];
    const int ctx = clen[b];

    if (tid < 64) {
        int i = tid;
        float invf = __bfloat162float(__float2bfloat16(1.0f / powf(10000.0f, (float)i * (1.0f / 64.0f))));
        float tb   = __bfloat162float(__float2bfloat16((float)ctx));
        float fr   = __bfloat162float(__float2bfloat16(tb * invf));
        float c = __bfloat162float(__float2bfloat16((float)cos((double)fr)));
        float s = __bfloat162float(__float2bfloat16((float)sin((double)fr)));
        cs[i] = c; cs[i + 64] = c;
        sn[i] = s; sn[i + 64] = s;
    }
    __syncthreads();

    // q: H*D = 4096 elems, pre-scaled by SCALE*log2e
    for (int idx = tid; idx < H * D; idx += 256) {
        int h = idx >> 7, d = idx & 127;
        const float* qp = q + ((size_t)(b * H + h)) * D;
        float x   = qp[d];
        float rot = (d < 64) ? -qp[d + 64] : qp[d - 64];
        g_qr[b][h][d] = (x * cs[d] + rot * sn[d]) * QF;
    }
    // k_new: HKV*D = 1024 elems
    for (int idx = tid; idx < HKV * D; idx += 256) {
        int h = idx >> 7, d = idx & 127;
        const float* kp = knew + ((size_t)(b * HKV + h)) * D;
        float x   = kp[d];
        float rot = (d < 64) ? -kp[d + 64] : kp[d - 64];
        g_kn[b][h][d] = x * cs[d] + rot * sn[d];
    }
}

// ---------------------------------------------------------------------------
// Kernel 1: persistent split-KV partials with work stealing.
// Item = (b, kvh, split). 8 warps, warp w owns tokens t0+w, t0+w+8, ...
// Lane j holds d-slice [4j, 4j+4).
// ---------------------------------------------------------------------------
__global__ __launch_bounds__(256, 3)
void attn_split_kernel(const float* __restrict__ vnew,
                       const float* __restrict__ kc,
                       const float* __restrict__ vc,
                       const int*   __restrict__ btab,
                       const int*   __restrict__ clen)
{
    const int tid  = threadIdx.x;
    const int wid  = tid >> 5;
    const int lane = tid & 31;
    const bool hi16 = (lane & 16) != 0;
    const bool hi8  = (lane & 8)  != 0;
    const int grp   = lane >> 3;

    // racc is stored via float4 (STS.128): MUST be 16B aligned. Static smem
    // arrays default to element alignment (4B) — the R4/R5 trap.
    __shared__ __align__(16) float racc[8][GRP][D];
    __shared__ float rl[8][GRP];
    __shared__ int   bt[BPS];
    __shared__ int   s_item;

    const float4* kc4 = reinterpret_cast<const float4*>(kc);
    const float4* vc4 = reinterpret_cast<const float4*>(vc);

    for (;;) {
        __syncthreads();                 // previous item fully consumed (bt reuse safe)
        if (tid == 0) s_item = atomicAdd(&g_ctr, 1);
        __syncthreads();
        const int item = s_item;
        if (item >= NITEMS) return;

        const int split = item % NSPLIT;
        const int kvh   = (item / NSPLIT) % HKV;
        const int b     = item / (NSPLIT * HKV);

        const int ctx = clen[b];
        const int t0  = split * SPLIT;
        if (t0 >= ctx) continue;

        const int t1   = min(t0 + SPLIT, ctx);
        const int last = ctx - 1;
        const int tcut = min(t1, last);
        const int pbase = ((b * HKV + kvh) * NSPLIT + split) * GRP;

        if (tid < BPS) bt[tid] = btab[b * BPS + tid];
        __syncthreads();

        const float4 qv0 = *reinterpret_cast<const float4*>(&g_qr[b][kvh * GRP + 0][lane * 4]);
        const float4 qv1 = *reinterpret_cast<const float4*>(&g_qr[b][kvh * GRP + 1][lane * 4]);
        const float4 qv2 = *reinterpret_cast<const float4*>(&g_qr[b][kvh * GRP + 2][lane * 4]);
        const float4 qv3 = *reinterpret_cast<const float4*>(&g_qr[b][kvh * GRP + 3][lane * 4]);

        float  l0 = 0.f, l1 = 0.f, l2 = 0.f, l3 = 0.f;
        float4 a0 = make_float4(0,0,0,0), a1 = a0, a2 = a0, a3 = a0;

        auto process = [&](float4 k4, float4 v4) {
            float p0 = k4.x*qv0.x + k4.y*qv0.y + k4.z*qv0.z + k4.w*qv0.w;
            float p1 = k4.x*qv1.x + k4.y*qv1.y + k4.z*qv1.z + k4.w*qv1.w;
            float p2 = k4.x*qv2.x + k4.y*qv2.y + k4.z*qv2.z + k4.w*qv2.w;
            float p3 = k4.x*qv3.x + k4.y*qv3.y + k4.z*qv3.z + k4.w*qv3.w;
            // multi-value allreduce: 9 shuffles; head slot j on this lane = (j ^ grp)
            float gA0 = hi16 ? p0 : p2;
            float gA1 = hi16 ? p1 : p3;
            float r0  = hi16 ? p2 : p0;
            float r1  = hi16 ? p3 : p1;
            r0 += __shfl_xor_sync(0xffffffffu, gA0, 16);
            r1 += __shfl_xor_sync(0xffffffffu, gA1, 16);
            float gB = hi8 ? r0 : r1;
            float r  = hi8 ? r1 : r0;
            r += __shfl_xor_sync(0xffffffffu, gB, 8);
            r += __shfl_xor_sync(0xffffffffu, r, 4);
            r += __shfl_xor_sync(0xffffffffu, r, 2);
            r += __shfl_xor_sync(0xffffffffu, r, 1);
            float s1 = __shfl_xor_sync(0xffffffffu, r, 8);
            float s2 = __shfl_xor_sync(0xffffffffu, r, 16);
            float s3 = __shfl_xor_sync(0xffffffffu, r, 24);
            float p;
            p = ex2(r  + M0C); l0 += p;
            a0.x += p*v4.x; a0.y += p*v4.y; a0.z += p*v4.z; a0.w += p*v4.w;
            p = ex2(s1 + M0C); l1 += p;
            a1.x += p*v4.x; a1.y += p*v4.y; a1.z += p*v4.z; a1.w += p*v4.w;
            p = ex2(s2 + M0C); l2 += p;
            a2.x += p*v4.x; a2.y += p*v4.y; a2.z += p*v4.z; a2.w += p*v4.w;
            p = ex2(s3 + M0C); l3 += p;
            a3.x += p*v4.x; a3.y += p*v4.y; a3.z += p*v4.z; a3.w += p*v4.w;
        };

        const int hk = kvh * 32 + lane;

        // main loop over cached tokens, prefetch depth 2
        {
            int t = t0 + wid;
            float4 z = make_float4(0,0,0,0);
            float4 k0 = z, v0 = z, k1 = z, v1 = z;
            if (t < tcut) {
                int idx = bt[t >> 4] * 4096 + (t & 15) * 256 + hk;
                k0 = kc4[idx]; v0 = vc4[idx];
            }
            if (t + 8 < tcut) {
                int tn = t + 8;
                int idx = bt[tn >> 4] * 4096 + (tn & 15) * 256 + hk;
                k1 = kc4[idx]; v1 = vc4[idx];
            }
            #pragma unroll 2
            while (t < tcut) {
                float4 k2 = z, v2 = z;
                int tp = t + 16;
                if (tp < tcut) {
                    int idx = bt[tp >> 4] * 4096 + (tp & 15) * 256 + hk;
                    k2 = kc4[idx]; v2 = vc4[idx];
                }
                process(k0, v0);
                k0 = k1; v0 = v1; k1 = k2; v1 = v2;
                t += 8;
            }
        }

        // new token (index last): pre-roped k_new + v_new
        if (last >= t0 && last < t1 && wid == ((last - t0) & 7)) {
            float4 k4 = *reinterpret_cast<const float4*>(&g_kn[b][kvh][lane * 4]);
            float4 v4 = reinterpret_cast<const float4*>(vnew + ((size_t)(b * HKV + kvh)) * D)[lane];
            process(k4, v4);
        }

        // cross-warp combine (plain sums under shared fixed shift)
        *reinterpret_cast<float4*>(&racc[wid][0 ^ grp][lane * 4]) = a0;
        *reinterpret_cast<float4*>(&racc[wid][1 ^ grp][lane * 4]) = a1;
        *reinterpret_cast<float4*>(&racc[wid][2 ^ grp][lane * 4]) = a2;
        *reinterpret_cast<float4*>(&racc[wid][3 ^ grp][lane * 4]) = a3;
        if (lane == 0) {  // lane 0: grp 0, slot j == head j
            rl[wid][0] = l0; rl[wid][1] = l1; rl[wid][2] = l2; rl[wid][3] = l3;
        }
        __syncthreads();

        for (int idx = tid; idx < GRP * D; idx += 256) {
            int g = idx >> 7, d = idx & 127;
            float A = 0.f;
#pragma unroll
            for (int w = 0; w < 8; w++) A += racc[w][g][d];
            g_pout[(size_t)(pbase + g) * D + d] = A;
            if (d == 0) {
                float L = 0.f;
#pragma unroll
                for (int w = 0; w < 8; w++) L += rl[w][g];
                g_pl[pbase + g] = L;
            }
        }
    }
}

// ---------------------------------------------------------------------------
// Kernel 2: combine. grid = B*HKV (256), 256 threads; thread handles 2 (g,d) elems.
// ---------------------------------------------------------------------------
__global__ __launch_bounds__(256)
void attn_combine_kernel(float* __restrict__ out, const int* __restrict__ clen)
{
    const int bk  = blockIdx.x;          // b*HKV + kvh
    const int b   = bk / HKV;
    const int ns  = (clen[b] + SPLIT - 1) / SPLIT;

#pragma unroll
    for (int e = 0; e < 2; e++) {
        int idx = threadIdx.x + e * 256;      // [0, 512)
        int g = idx >> 7, d = idx & 127;
        float A = 0.f, L = 0.f;
#pragma unroll
        for (int s = 0; s < NSPLIT; s++) {
            if (s < ns) {
                int pg = (bk * NSPLIT + s) * GRP + g;
                A += g_pout[(size_t)pg * D + d];
                L += g_pl[pg];
            }
        }
        int h = (bk % HKV) * GRP + g;
        out[((size_t)(b * H + h)) * D + d] = A / L;
    }
}

// ---------------------------------------------------------------------------
extern "C" void kernel_launch(void* const* d_in, const int* in_sizes, int n_in,
                              void* d_out, int out_size)
{
    const float* q    = (const float*)d_in[0];
    const float* knew = (const float*)d_in[1];
    const float* vnew = (const float*)d_in[2];
    const float* kc   = (const float*)d_in[3];
    const float* vc   = (const float*)d_in[4];
    const int*   btab = (const int*)d_in[5];
    const int*   clen = (const int*)d_in[6];
    float* out = (float*)d_out;

    prep_kernel<<<B, 256>>>(q, knew, clen);
    attn_split_kernel<<<148 * 3, 256>>>(vnew, kc, vc, btab, clen);
    attn_combine_kernel<<<B * HKV, 256>>>(out, clen);
}

// round 9
// speedup vs baseline: 1.1379x; 1.0046x over previous
#include <cuda_runtime.h>
#include <cuda_bf16.h>
#include <math.h>

constexpr int B    = 32;
constexpr int H    = 32;
constexpr int HKV  = 8;
constexpr int GRP  = H / HKV;     // 4
constexpr int D    = 128;
constexpr int BPS  = 128;
constexpr int NSPLIT = 8;
constexpr int SPLIT  = 256;
constexpr int NITEMS = B * HKV * NSPLIT;   // 2048
constexpr float SCALE = 0.08838834764831845f;
constexpr float LOG2E = 1.4426950408889634f;
constexpr float QF    = SCALE * LOG2E;
constexpr float M0C   = -16.0f * LOG2E;    // fixed softmax shift (log2 units)

// 16B alignment required: accessed through float4.
__device__ __align__(16) float g_pout[B * HKV * NSPLIT * GRP * D];
__device__ float g_pl[B * HKV * NSPLIT * GRP];
__device__ __align__(16) float g_qr[B][H][D];     // roped, pre-scaled q
__device__ __align__(16) float g_kn[B][HKV][D];   // roped k_new
__device__ int   g_ctr;

__device__ __forceinline__ float ex2(float x) {
    float r;
    asm("ex2.approx.f32 %0, %1;" : "=f"(r) : "f"(x));
    return r;
}

// Cheap exact-enough range reduction: r = x - rint(x/2pi)*2pi, in double with
// hi/lo split of 2pi. Input x <= ~2048 (bf16 product, exactly representable).
// Error < 1e-13 rad; then float sin/cos on r in [-pi, pi]. ~5 FP64 ops instead
// of libdevice's full double trig (~hundreds) — that path was 14.75us of R7.
__device__ __forceinline__ void sincos_bf16safe(float x, float* s, float* c) {
    const double TWO_PI_HI = 6.283185307179586;      // 2pi rounded
    const double TWO_PI_LO = 2.4492935982947064e-16; // residual
    double xd = (double)x;
    double k  = rint(xd * 0.15915494309189535);      // x / 2pi
    double r  = (xd - k * TWO_PI_HI) - k * TWO_PI_LO;
    float rf = (float)r;
    *s = sinf(rf);
    *c = cosf(rf);
}

// ---------------------------------------------------------------------------
// Kernel 0: per-b prep — RoPE tables (bf16-faithful), roped q / k_new, counter reset
// ---------------------------------------------------------------------------
__global__ __launch_bounds__(256)
void prep_kernel(const float* __restrict__ q,
                 const float* __restrict__ knew,
                 const int*   __restrict__ clen)
{
    const int b   = blockIdx.x;
    const int tid = threadIdx.x;
    if (b == 0 && tid == 0) g_ctr = 0;

    __shared__ float cs[D], sn[D];
    const int ctx = clen[b];

    if (tid < 64) {
        int i = tid;
        float invf = __bfloat162float(__float2bfloat16(1.0f / powf(10000.0f, (float)i * (1.0f / 64.0f))));
        float tb   = __bfloat162float(__float2bfloat16((float)ctx));
        float fr   = __bfloat162float(__float2bfloat16(tb * invf));
        float sf, cf;
        sincos_bf16safe(fr, &sf, &cf);
        float c = __bfloat162float(__float2bfloat16(cf));
        float s = __bfloat162float(__float2bfloat16(sf));
        cs[i] = c; cs[i + 64] = c;
        sn[i] = s; sn[i + 64] = s;
    }
    __syncthreads();

    // q: H*D = 4096 elems, pre-scaled by SCALE*log2e
    for (int idx = tid; idx < H * D; idx += 256) {
        int h = idx >> 7, d = idx & 127;
        const float* qp = q + ((size_t)(b * H + h)) * D;
        float x   = qp[d];
        float rot = (d < 64) ? -qp[d + 64] : qp[d - 64];
        g_qr[b][h][d] = (x * cs[d] + rot * sn[d]) * QF;
    }
    // k_new: HKV*D = 1024 elems
    for (int idx = tid; idx < HKV * D; idx += 256) {
        int h = idx >> 7, d = idx & 127;
        const float* kp = knew + ((size_t)(b * HKV + h)) * D;
        float x   = kp[d];
        float rot = (d < 64) ? -kp[d + 64] : kp[d - 64];
        g_kn[b][h][d] = x * cs[d] + rot * sn[d];
    }
}

// ---------------------------------------------------------------------------
// Kernel 1: persistent split-KV partials with work stealing.
// Item = (b, kvh, split). 8 warps, warp w owns tokens t0+w, t0+w+8, ...
// Lane j holds d-slice [4j, 4j+4).
// ---------------------------------------------------------------------------
__global__ __launch_bounds__(256, 3)
void attn_split_kernel(const float* __restrict__ vnew,
                       const float* __restrict__ kc,
                       const float* __restrict__ vc,
                       const int*   __restrict__ btab,
                       const int*   __restrict__ clen)
{
    const int tid  = threadIdx.x;
    const int wid  = tid >> 5;
    const int lane = tid & 31;
    const bool hi16 = (lane & 16) != 0;
    const bool hi8  = (lane & 8)  != 0;
    const int grp   = lane >> 3;

    // stored via float4 (STS.128): must be 16B aligned.
    __shared__ __align__(16) float racc[8][GRP][D];
    __shared__ float rl[8][GRP];
    __shared__ int   bt[BPS];
    __shared__ int   s_item;

    const float4* kc4 = reinterpret_cast<const float4*>(kc);
    const float4* vc4 = reinterpret_cast<const float4*>(vc);

    for (;;) {
        __syncthreads();                 // previous item fully consumed (bt reuse safe)
        if (tid == 0) s_item = atomicAdd(&g_ctr, 1);
        __syncthreads();
        const int item = s_item;
        if (item >= NITEMS) return;

        const int split = item % NSPLIT;
        const int kvh   = (item / NSPLIT) % HKV;
        const int b     = item / (NSPLIT * HKV);

        const int ctx = clen[b];
        const int t0  = split * SPLIT;
        if (t0 >= ctx) continue;

        const int t1   = min(t0 + SPLIT, ctx);
        const int last = ctx - 1;
        const int tcut = min(t1, last);
        const int pbase = ((b * HKV + kvh) * NSPLIT + split) * GRP;

        if (tid < BPS) bt[tid] = btab[b * BPS + tid];
        __syncthreads();

        const float4 qv0 = *reinterpret_cast<const float4*>(&g_qr[b][kvh * GRP + 0][lane * 4]);
        const float4 qv1 = *reinterpret_cast<const float4*>(&g_qr[b][kvh * GRP + 1][lane * 4]);
        const float4 qv2 = *reinterpret_cast<const float4*>(&g_qr[b][kvh * GRP + 2][lane * 4]);
        const float4 qv3 = *reinterpret_cast<const float4*>(&g_qr[b][kvh * GRP + 3][lane * 4]);

        float  l0 = 0.f, l1 = 0.f, l2 = 0.f, l3 = 0.f;
        float4 a0 = make_float4(0,0,0,0), a1 = a0, a2 = a0, a3 = a0;

        auto process = [&](float4 k4, float4 v4) {
            float p0 = k4.x*qv0.x + k4.y*qv0.y + k4.z*qv0.z + k4.w*qv0.w;
            float p1 = k4.x*qv1.x + k4.y*qv1.y + k4.z*qv1.z + k4.w*qv1.w;
            float p2 = k4.x*qv2.x + k4.y*qv2.y + k4.z*qv2.z + k4.w*qv2.w;
            float p3 = k4.x*qv3.x + k4.y*qv3.y + k4.z*qv3.z + k4.w*qv3.w;
            // multi-value allreduce: 9 shuffles; head slot j on this lane = (j ^ grp)
            float gA0 = hi16 ? p0 : p2;
            float gA1 = hi16 ? p1 : p3;
            float r0  = hi16 ? p2 : p0;
            float r1  = hi16 ? p3 : p1;
            r0 += __shfl_xor_sync(0xffffffffu, gA0, 16);
            r1 += __shfl_xor_sync(0xffffffffu, gA1, 16);
            float gB = hi8 ? r0 : r1;
            float r  = hi8 ? r1 : r0;
            r += __shfl_xor_sync(0xffffffffu, gB, 8);
            r += __shfl_xor_sync(0xffffffffu, r, 4);
            r += __shfl_xor_sync(0xffffffffu, r, 2);
            r += __shfl_xor_sync(0xffffffffu, r, 1);
            float s1 = __shfl_xor_sync(0xffffffffu, r, 8);
            float s2 = __shfl_xor_sync(0xffffffffu, r, 16);
            float s3 = __shfl_xor_sync(0xffffffffu, r, 24);
            float p;
            p = ex2(r  + M0C); l0 += p;
            a0.x += p*v4.x; a0.y += p*v4.y; a0.z += p*v4.z; a0.w += p*v4.w;
            p = ex2(s1 + M0C); l1 += p;
            a1.x += p*v4.x; a1.y += p*v4.y; a1.z += p*v4.z; a1.w += p*v4.w;
            p = ex2(s2 + M0C); l2 += p;
            a2.x += p*v4.x; a2.y += p*v4.y; a2.z += p*v4.z; a2.w += p*v4.w;
            p = ex2(s3 + M0C); l3 += p;
            a3.x += p*v4.x; a3.y += p*v4.y; a3.z += p*v4.z; a3.w += p*v4.w;
        };

        const int hk = kvh * 32 + lane;

        // main loop over cached tokens, prefetch depth 2
        {
            int t = t0 + wid;
            float4 z = make_float4(0,0,0,0);
            float4 k0 = z, v0 = z, k1 = z, v1 = z;
            if (t < tcut) {
                int idx = bt[t >> 4] * 4096 + (t & 15) * 256 + hk;
                k0 = kc4[idx]; v0 = vc4[idx];
            }
            if (t + 8 < tcut) {
                int tn = t + 8;
                int idx = bt[tn >> 4] * 4096 + (tn & 15) * 256 + hk;
                k1 = kc4[idx]; v1 = vc4[idx];
            }
            #pragma unroll 2
            while (t < tcut) {
                float4 k2 = z, v2 = z;
                int tp = t + 16;
                if (tp < tcut) {
                    int idx = bt[tp >> 4] * 4096 + (tp & 15) * 256 + hk;
                    k2 = kc4[idx]; v2 = vc4[idx];
                }
                process(k0, v0);
                k0 = k1; v0 = v1; k1 = k2; v1 = v2;
                t += 8;
            }
        }

        // new token (index last): pre-roped k_new + v_new
        if (last >= t0 && last < t1 && wid == ((last - t0) & 7)) {
            float4 k4 = *reinterpret_cast<const float4*>(&g_kn[b][kvh][lane * 4]);
            float4 v4 = reinterpret_cast<const float4*>(vnew + ((size_t)(b * HKV + kvh)) * D)[lane];
            process(k4, v4);
        }

        // cross-warp combine (plain sums under shared fixed shift)
        *reinterpret_cast<float4*>(&racc[wid][0 ^ grp][lane * 4]) = a0;
        *reinterpret_cast<float4*>(&racc[wid][1 ^ grp][lane * 4]) = a1;
        *reinterpret_cast<float4*>(&racc[wid][2 ^ grp][lane * 4]) = a2;
        *reinterpret_cast<float4*>(&racc[wid][3 ^ grp][lane * 4]) = a3;
        if (lane == 0) {  // lane 0: grp 0, slot j == head j
            rl[wid][0] = l0; rl[wid][1] = l1; rl[wid][2] = l2; rl[wid][3] = l3;
        }
        __syncthreads();

        for (int idx = tid; idx < GRP * D; idx += 256) {
            int g = idx >> 7, d = idx & 127;
            float A = 0.f;
#pragma unroll
            for (int w = 0; w < 8; w++) A += racc[w][g][d];
            g_pout[(size_t)(pbase + g) * D + d] = A;
            if (d == 0) {
                float L = 0.f;
#pragma unroll
                for (int w = 0; w < 8; w++) L += rl[w][g];
                g_pl[pbase + g] = L;
            }
        }
    }
}

// ---------------------------------------------------------------------------
// Kernel 2: combine. grid = B*HKV (256), 256 threads; thread handles 2 (g,d) elems.
// ---------------------------------------------------------------------------
__global__ __launch_bounds__(256)
void attn_combine_kernel(float* __restrict__ out, const int* __restrict__ clen)
{
    const int bk  = blockIdx.x;          // b*HKV + kvh
    const int b   = bk / HKV;
    const int ns  = (clen[b] + SPLIT - 1) / SPLIT;

#pragma unroll
    for (int e = 0; e < 2; e++) {
        int idx = threadIdx.x + e * 256;      // [0, 512)
        int g = idx >> 7, d = idx & 127;
        float A = 0.f, L = 0.f;
#pragma unroll
        for (int s = 0; s < NSPLIT; s++) {
            if (s < ns) {
                int pg = (bk * NSPLIT + s) * GRP + g;
                A += g_pout[(size_t)pg * D + d];
                L += g_pl[pg];
            }
        }
        int h = (bk % HKV) * GRP + g;
        out[((size_t)(b * H + h)) * D + d] = A / L;
    }
}

// ---------------------------------------------------------------------------
extern "C" void kernel_launch(void* const* d_in, const int* in_sizes, int n_in,
                              void* d_out, int out_size)
{
    const float* q    = (const float*)d_in[0];
    const float* knew = (const float*)d_in[1];
    const float* vnew = (const float*)d_in[2];
    const float* kc   = (const float*)d_in[3];
    const float* vc   = (const float*)d_in[4];
    const int*   btab = (const int*)d_in[5];
    const int*   clen = (const int*)d_in[6];
    float* out = (float*)d_out;

    prep_kernel<<<B, 256>>>(q, knew, clen);
    attn_split_kernel<<<148 * 3, 256>>>(vnew, kc, vc, btab, clen);
    attn_combine_kernel<<<B * HKV, 256>>>(out, clen);
}

// round 10
// speedup vs baseline: 1.3073x; 1.1489x over previous
#include <cuda_runtime.h>
#include <cuda_bf16.h>
#include <math.h>

constexpr int B    = 32;
constexpr int H    = 32;
constexpr int HKV  = 8;
constexpr int GRP  = H / HKV;     // 4
constexpr int D    = 128;
constexpr int BPS  = 128;
constexpr int NSPLIT = 8;
constexpr int SPLIT  = 256;
constexpr int NITEMS = B * HKV * NSPLIT;   // 2048
constexpr float SCALE = 0.08838834764831845f;
constexpr float LOG2E = 1.4426950408889634f;
constexpr float QF    = SCALE * LOG2E;
constexpr float M0C   = -16.0f * LOG2E;    // fixed softmax shift (log2 units)

// 16B alignment required: accessed through float4.
__device__ __align__(16) float g_pout[B * HKV * NSPLIT * GRP * D];
__device__ float g_pl[B * HKV * NSPLIT * GRP];
__device__ __align__(16) float g_qr[B][H][D];     // roped, pre-scaled q
__device__ __align__(16) float g_kn[B][HKV][D];   // roped k_new
__device__ int   g_ctr;

__device__ __forceinline__ float ex2(float x) {
    float r;
    asm("ex2.approx.f32 %0, %1;" : "=f"(r) : "f"(x));
    return r;
}

// Exact-enough range reduction (~5 FP64 ops): r = x - rint(x/2pi)*2pi with
// hi/lo split 2pi; error < 1e-13 rad; float sin/cos on r in [-pi,pi] is then
// accurate far below bf16 ulp regardless of fast-math.
__device__ __forceinline__ void sincos_bf16safe(float x, float* s, float* c) {
    const double TWO_PI_HI = 6.283185307179586;
    const double TWO_PI_LO = 2.4492935982947064e-16;
    double xd = (double)x;
    double k  = rint(xd * 0.15915494309189535);
    double r  = (xd - k * TWO_PI_HI) - k * TWO_PI_LO;
    float rf = (float)r;
    *s = sinf(rf);
    *c = cosf(rf);
}

// ---------------------------------------------------------------------------
// Kernel 0: prep, fully parallel / loop-free rope.
// grid = B*5 CTAs; CTA handles 8 of the 40 head-rows (32 q + 8 k_new) of one b.
// Warp w = one row; lane = one float4 of D. Two float4 loads per lane, no chains.
// ---------------------------------------------------------------------------
__global__ __launch_bounds__(256)
void prep_kernel(const float* __restrict__ q,
                 const float* __restrict__ knew,
                 const int*   __restrict__ clen)
{
    const int b     = blockIdx.x / 5;
    const int slice = blockIdx.x % 5;
    const int tid   = threadIdx.x;
    const int wid   = tid >> 5;
    const int lane  = tid & 31;
    if (blockIdx.x == 0 && tid == 0) g_ctr = 0;

    __shared__ float cs[64], sn[64];
    const int ctx = clen[b];

    if (tid < 64) {
        int i = tid;
        float invf = __bfloat162float(__float2bfloat16(1.0f / powf(10000.0f, (float)i * (1.0f / 64.0f))));
        float tb   = __bfloat162float(__float2bfloat16((float)ctx));
        float fr   = __bfloat162float(__float2bfloat16(tb * invf));
        float sf, cf;
        sincos_bf16safe(fr, &sf, &cf);
        cs[i] = __bfloat162float(__float2bfloat16(cf));
        sn[i] = __bfloat162float(__float2bfloat16(sf));
    }
    __syncthreads();

    const int row = slice * 8 + wid;          // 0..39
    const bool isq = row < H;
    const float* src = isq ? (q    + ((size_t)(b * H   + row)      ) * D)
                           : (knew + ((size_t)(b * HKV + (row - H))) * D);
    const int d0 = lane * 4;
    // both halves loaded as float4: x = src[d0..d0+3], y = src[(d0^64)..]
    float4 x4 = reinterpret_cast<const float4*>(src)[lane];
    float4 y4 = reinterpret_cast<const float4*>(src)[lane ^ 16];
    const float sgn = (lane < 16) ? -1.0f : 1.0f;
    const int ti = (lane & 15) * 4;           // trig table index base (d % 64)
    const float f = isq ? QF : 1.0f;

    float4 o;
    o.x = (x4.x * cs[ti+0] + sgn * y4.x * sn[ti+0]) * f;
    o.y = (x4.y * cs[ti+1] + sgn * y4.y * sn[ti+1]) * f;
    o.z = (x4.z * cs[ti+2] + sgn * y4.z * sn[ti+2]) * f;
    o.w = (x4.w * cs[ti+3] + sgn * y4.w * sn[ti+3]) * f;

    float* dst = isq ? &g_qr[b][row][d0] : &g_kn[b][row - H][d0];
    *reinterpret_cast<float4*>(dst) = o;
}

// ---------------------------------------------------------------------------
// Kernel 1: persistent split-KV partials with work stealing.
// Item = (b, kvh, split). 8 warps, warp w owns tokens t0+w, t0+w+8, ...
// Lane j holds d-slice [4j, 4j+4).
// ---------------------------------------------------------------------------
__global__ __launch_bounds__(256, 3)
void attn_split_kernel(const float* __restrict__ vnew,
                       const float* __restrict__ kc,
                       const float* __restrict__ vc,
                       const int*   __restrict__ btab,
                       const int*   __restrict__ clen)
{
    const int tid  = threadIdx.x;
    const int wid  = tid >> 5;
    const int lane = tid & 31;
    const bool hi16 = (lane & 16) != 0;
    const bool hi8  = (lane & 8)  != 0;
    const int grp   = lane >> 3;

    __shared__ __align__(16) float racc[8][GRP][D];
    __shared__ float rl[8][GRP];
    __shared__ int   bt[BPS];
    __shared__ int   s_item;

    const float4* kc4 = reinterpret_cast<const float4*>(kc);
    const float4* vc4 = reinterpret_cast<const float4*>(vc);

    for (;;) {
        __syncthreads();
        if (tid == 0) s_item = atomicAdd(&g_ctr, 1);
        __syncthreads();
        const int item = s_item;
        if (item >= NITEMS) return;

        const int split = item % NSPLIT;
        const int kvh   = (item / NSPLIT) % HKV;
        const int b     = item / (NSPLIT * HKV);

        const int ctx = clen[b];
        const int t0  = split * SPLIT;
        if (t0 >= ctx) continue;

        const int t1   = min(t0 + SPLIT, ctx);
        const int last = ctx - 1;
        const int tcut = min(t1, last);
        const int pbase = ((b * HKV + kvh) * NSPLIT + split) * GRP;

        if (tid < BPS) bt[tid] = btab[b * BPS + tid];
        __syncthreads();

        const float4 qv0 = *reinterpret_cast<const float4*>(&g_qr[b][kvh * GRP + 0][lane * 4]);
        const float4 qv1 = *reinterpret_cast<const float4*>(&g_qr[b][kvh * GRP + 1][lane * 4]);
        const float4 qv2 = *reinterpret_cast<const float4*>(&g_qr[b][kvh * GRP + 2][lane * 4]);
        const float4 qv3 = *reinterpret_cast<const float4*>(&g_qr[b][kvh * GRP + 3][lane * 4]);

        float  l0 = 0.f, l1 = 0.f, l2 = 0.f, l3 = 0.f;
        float4 a0 = make_float4(0,0,0,0), a1 = a0, a2 = a0, a3 = a0;

        auto process = [&](float4 k4, float4 v4) {
            float p0 = k4.x*qv0.x + k4.y*qv0.y + k4.z*qv0.z + k4.w*qv0.w;
            float p1 = k4.x*qv1.x + k4.y*qv1.y + k4.z*qv1.z + k4.w*qv1.w;
            float p2 = k4.x*qv2.x + k4.y*qv2.y + k4.z*qv2.z + k4.w*qv2.w;
            float p3 = k4.x*qv3.x + k4.y*qv3.y + k4.z*qv3.z + k4.w*qv3.w;
            float gA0 = hi16 ? p0 : p2;
            float gA1 = hi16 ? p1 : p3;
            float r0  = hi16 ? p2 : p0;
            float r1  = hi16 ? p3 : p1;
            r0 += __shfl_xor_sync(0xffffffffu, gA0, 16);
            r1 += __shfl_xor_sync(0xffffffffu, gA1, 16);
            float gB = hi8 ? r0 : r1;
            float r  = hi8 ? r1 : r0;
            r += __shfl_xor_sync(0xffffffffu, gB, 8);
            r += __shfl_xor_sync(0xffffffffu, r, 4);
            r += __shfl_xor_sync(0xffffffffu, r, 2);
            r += __shfl_xor_sync(0xffffffffu, r, 1);
            float s1 = __shfl_xor_sync(0xffffffffu, r, 8);
            float s2 = __shfl_xor_sync(0xffffffffu, r, 16);
            float s3 = __shfl_xor_sync(0xffffffffu, r, 24);
            float p;
            p = ex2(r  + M0C); l0 += p;
            a0.x += p*v4.x; a0.y += p*v4.y; a0.z += p*v4.z; a0.w += p*v4.w;
            p = ex2(s1 + M0C); l1 += p;
            a1.x += p*v4.x; a1.y += p*v4.y; a1.z += p*v4.z; a1.w += p*v4.w;
            p = ex2(s2 + M0C); l2 += p;
            a2.x += p*v4.x; a2.y += p*v4.y; a2.z += p*v4.z; a2.w += p*v4.w;
            p = ex2(s3 + M0C); l3 += p;
            a3.x += p*v4.x; a3.y += p*v4.y; a3.z += p*v4.z; a3.w += p*v4.w;
        };

        const int hk = kvh * 32 + lane;

        // main loop over cached tokens, prefetch depth 2
        {
            int t = t0 + wid;
            float4 z = make_float4(0,0,0,0);
            float4 k0 = z, v0 = z, k1 = z, v1 = z;
            if (t < tcut) {
                int idx = bt[t >> 4] * 4096 + (t & 15) * 256 + hk;
                k0 = kc4[idx]; v0 = vc4[idx];
            }
            if (t + 8 < tcut) {
                int tn = t + 8;
                int idx = bt[tn >> 4] * 4096 + (tn & 15) * 256 + hk;
                k1 = kc4[idx]; v1 = vc4[idx];
            }
            #pragma unroll 2
            while (t < tcut) {
                float4 k2 = z, v2 = z;
                int tp = t + 16;
                if (tp < tcut) {
                    int idx = bt[tp >> 4] * 4096 + (tp & 15) * 256 + hk;
                    k2 = kc4[idx]; v2 = vc4[idx];
                }
                process(k0, v0);
                k0 = k1; v0 = v1; k1 = k2; v1 = v2;
                t += 8;
            }
        }

        // new token (index last): pre-roped k_new + v_new
        if (last >= t0 && last < t1 && wid == ((last - t0) & 7)) {
            float4 k4 = *reinterpret_cast<const float4*>(&g_kn[b][kvh][lane * 4]);
            float4 v4 = reinterpret_cast<const float4*>(vnew + ((size_t)(b * HKV + kvh)) * D)[lane];
            process(k4, v4);
        }

        // cross-warp combine (plain sums under shared fixed shift)
        *reinterpret_cast<float4*>(&racc[wid][0 ^ grp][lane * 4]) = a0;
        *reinterpret_cast<float4*>(&racc[wid][1 ^ grp][lane * 4]) = a1;
        *reinterpret_cast<float4*>(&racc[wid][2 ^ grp][lane * 4]) = a2;
        *reinterpret_cast<float4*>(&racc[wid][3 ^ grp][lane * 4]) = a3;
        if (lane == 0) {
            rl[wid][0] = l0; rl[wid][1] = l1; rl[wid][2] = l2; rl[wid][3] = l3;
        }
        __syncthreads();

        for (int idx = tid; idx < GRP * D; idx += 256) {
            int g = idx >> 7, d = idx & 127;
            float A = 0.f;
#pragma unroll
            for (int w = 0; w < 8; w++) A += racc[w][g][d];
            g_pout[(size_t)(pbase + g) * D + d] = A;
            if (d == 0) {
                float L = 0.f;
#pragma unroll
                for (int w = 0; w < 8; w++) L += rl[w][g];
                g_pl[pbase + g] = L;
            }
        }
    }
}

// ---------------------------------------------------------------------------
// Kernel 2: combine. grid = B*HKV (256), 256 threads; thread handles 2 (g,d) elems.
// ---------------------------------------------------------------------------
__global__ __launch_bounds__(256)
void attn_combine_kernel(float* __restrict__ out, const int* __restrict__ clen)
{
    const int bk  = blockIdx.x;
    const int b   = bk / HKV;
    const int ns  = (clen[b] + SPLIT - 1) / SPLIT;

#pragma unroll
    for (int e = 0; e < 2; e++) {
        int idx = threadIdx.x + e * 256;
        int g = idx >> 7, d = idx & 127;
        float A = 0.f, L = 0.f;
#pragma unroll
        for (int s = 0; s < NSPLIT; s++) {
            if (s < ns) {
                int pg = (bk * NSPLIT + s) * GRP + g;
                A += g_pout[(size_t)pg * D + d];
                L += g_pl[pg];
            }
        }
        int h = (bk % HKV) * GRP + g;
        out[((size_t)(b * H + h)) * D + d] = A / L;
    }
}

// ---------------------------------------------------------------------------
extern "C" void kernel_launch(void* const* d_in, const int* in_sizes, int n_in,
                              void* d_out, int out_size)
{
    const float* q    = (const float*)d_in[0];
    const float* knew = (const float*)d_in[1];
    const float* vnew = (const float*)d_in[2];
    const float* kc   = (const float*)d_in[3];
    const float* vc   = (const float*)d_in[4];
    const int*   btab = (const int*)d_in[5];
    const int*   clen = (const int*)d_in[6];
    float* out = (float*)d_out;

    prep_kernel<<<B * 5, 256>>>(q, knew, clen);
    attn_split_kernel<<<148 * 3, 256>>>(vnew, kc, vc, btab, clen);
    attn_combine_kernel<<<B * HKV, 256>>>(out, clen);
}